// round 7
// baseline (speedup 1.0000x reference)
#include <cuda_runtime.h>
#include <math.h>
#include <cstdint>

#define N_ROWS 8192
#define N_COLS 512
#define GRID_A 512
#define THREADS_A 256
#define ROWS_PER_CTA 16                    /* 512 * 16 = 8192 */
#define TILE_BYTES (ROWS_PER_CTA * N_COLS * 4)   /* 32 KB */
#define NREP 8

#define SCALE_D   4294967296.0            /* 2^32 */
#define INV_SCALE (1.0 / 4294967296.0)

// Order-invariant integer accumulators (zero-init; last block resets).
__device__ unsigned long long g_col_ll[NREP][N_COLS];
__device__ unsigned long long g_S_ll;
__device__ int g_max_int;                 // bit-cast float, values >= 0
__device__ unsigned int g_counter;

__device__ __forceinline__ uint32_t smem_u32(const void* p) {
    uint32_t a;
    asm("{ .reg .u64 t; cvta.to.shared.u64 t, %1; cvt.u32.u64 %0, t; }"
        : "=r"(a) : "l"(p));
    return a;
}

__global__ void __launch_bounds__(THREADS_A)
fused_loss_kernel(const float* __restrict__ x, float* __restrict__ out) {
    __shared__ alignas(128) float s_tile[ROWS_PER_CTA * N_COLS];  // 32 KB
    __shared__ alignas(8) unsigned long long s_mbar;
    __shared__ float s_S[8];
    __shared__ float s_M[8];
    __shared__ double s_red[THREADS_A];
    __shared__ unsigned int s_last;

    const int tid = threadIdx.x;
    const int wid = tid >> 5;
    const int lid = tid & 31;

    const uint32_t mbar = smem_u32(&s_mbar);
    const uint32_t tile = smem_u32(s_tile);

    // ---- bulk-async copy: one 32 KB tile per CTA, engine-driven ----
    if (tid == 0) {
        asm volatile("mbarrier.init.shared.b64 [%0], 1;" :: "r"(mbar) : "memory");
    }
    __syncthreads();
    if (tid == 0) {
        asm volatile("mbarrier.arrive.expect_tx.shared.b64 _, [%0], %1;"
                     :: "r"(mbar), "r"((uint32_t)TILE_BYTES) : "memory");
        const float* src = x + (size_t)blockIdx.x * ROWS_PER_CTA * N_COLS;
        asm volatile(
            "cp.async.bulk.shared::cta.global.mbarrier::complete_tx::bytes "
            "[%0], [%1], %2, [%3];"
            :: "r"(tile), "l"(src), "r"((uint32_t)TILE_BYTES), "r"(mbar)
            : "memory");
    }
    // all threads wait for tile arrival (acquire)
    {
        uint32_t done;
        asm volatile(
            "{\n\t.reg .pred p;\n\t"
            "mbarrier.try_wait.parity.acquire.cta.shared::cta.b64 p, [%1], %2, 0x989680;\n\t"
            "selp.b32 %0, 1, 0, p;\n\t}"
            : "=r"(done) : "r"(mbar), "r"(0u) : "memory");
        if (!done) {
            asm volatile(
                "{\n\t.reg .pred P1;\n\t"
                "WL_%=:\n\t"
                "mbarrier.try_wait.parity.acquire.cta.shared::cta.b64 P1, [%0], %1, 0x989680;\n\t"
                "@P1 bra.uni WD_%=;\n\t"
                "bra.uni WL_%=;\n\t"
                "WD_%=:\n\t}"
                :: "r"(mbar), "r"(0u) : "memory");
        }
    }

    // ---- pass 1: row squared norms (warp per row, 2 rows per warp) ----
    float sq0 = 0.f, sq1 = 0.f;
    {
        const float4* t4 = reinterpret_cast<const float4*>(s_tile);
        const int r0 = wid * 2;
        #pragma unroll
        for (int p = 0; p < 4; ++p) {
            const float4 a = t4[r0 * 128 + p * 32 + lid];
            const float4 b = t4[(r0 + 1) * 128 + p * 32 + lid];
            sq0 += a.x * a.x + a.y * a.y + a.z * a.z + a.w * a.w;
            sq1 += b.x * b.x + b.y * b.y + b.z * b.z + b.w * b.w;
        }
        #pragma unroll
        for (int off = 16; off > 0; off >>= 1) {
            sq0 += __shfl_xor_sync(0xffffffffu, sq0, off);
            sq1 += __shfl_xor_sync(0xffffffffu, sq1, off);
        }
        if (lid == 0) {
            s_S[wid] = sq0 + sq1;
            s_M[wid] = fmaxf(sq0, sq1);
        }
    }

    // ---- pass 2: column sums (threads 0..127, float4 chunk each) ----
    const int rep = blockIdx.x & (NREP - 1);
    if (tid < 128) {
        const float4* t4 = reinterpret_cast<const float4*>(s_tile);
        float4 acc = make_float4(0.f, 0.f, 0.f, 0.f);
        #pragma unroll
        for (int r = 0; r < ROWS_PER_CTA; ++r) {
            const float4 v = t4[r * 128 + tid];
            acc.x += v.x; acc.y += v.y; acc.z += v.z; acc.w += v.w;
        }
        const int c = tid * 4;
        atomicAdd(&g_col_ll[rep][c + 0],
                  (unsigned long long)__double2ll_rn((double)acc.x * SCALE_D));
        atomicAdd(&g_col_ll[rep][c + 1],
                  (unsigned long long)__double2ll_rn((double)acc.y * SCALE_D));
        atomicAdd(&g_col_ll[rep][c + 2],
                  (unsigned long long)__double2ll_rn((double)acc.z * SCALE_D));
        atomicAdd(&g_col_ll[rep][c + 3],
                  (unsigned long long)__double2ll_rn((double)acc.w * SCALE_D));
    }
    __syncthreads();

    if (tid == 0) {
        float Sp = 0.f, Mp = 0.f;
        #pragma unroll
        for (int w = 0; w < 8; ++w) {
            Sp += s_S[w];
            Mp = fmaxf(Mp, s_M[w]);
        }
        atomicAdd(&g_S_ll, (unsigned long long)__double2ll_rn((double)Sp * SCALE_D));
        atomicMax(&g_max_int, __float_as_int(Mp));
        __threadfence();
        const unsigned int prev = atomicAdd(&g_counter, 1u);
        s_last = (prev == (unsigned int)(GRID_A - 1)) ? 1u : 0u;
    }
    __syncthreads();
    if (s_last == 0u) return;

    // ---- finalize: last block; accumulators tiny and L2-hot ----
    __threadfence();

    long long t0 = 0ll, t1 = 0ll;
    #pragma unroll
    for (int r = 0; r < NREP; ++r) {
        t0 += (long long)g_col_ll[r][tid];
        t1 += (long long)g_col_ll[r][tid + THREADS_A];
    }
    const double d0 = (double)t0 * INV_SCALE;
    const double d1 = (double)t1 * INV_SCALE;

    s_red[tid] = d0 * d0 + d1 * d1;
    __syncthreads();
    #pragma unroll
    for (int s = THREADS_A / 2; s > 0; s >>= 1) {
        if (tid < s) s_red[tid] += s_red[tid + s];
        __syncthreads();
    }
    // all reads of g_col_ll done (barrier above) -> safe to reset
    #pragma unroll
    for (int r = 0; r < NREP; ++r) {
        g_col_ll[r][tid] = 0ull;
        g_col_ll[r][tid + THREADS_A] = 0ull;
    }

    if (tid == 0) {
        const double ssq_total = s_red[0];
        const double S_total = (double)(long long)g_S_ll * INV_SCALE;
        const double maxsq = (double)__int_as_float(g_max_int);
        const double numer = (double)N_ROWS * S_total - ssq_total;
        const double norm = sqrt(maxsq);
        const double count = (double)N_ROWS * (double)(N_ROWS - 1) * 0.5;
        out[0] = (float)(numer / (norm * count));
        g_S_ll = 0ull;
        g_max_int = 0;
        g_counter = 0u;
    }
}

extern "C" void kernel_launch(void* const* d_in, const int* in_sizes, int n_in,
                              void* d_out, int out_size) {
    (void)in_sizes; (void)n_in; (void)out_size;
    const float* x = (const float*)d_in[0];
    float* out = (float*)d_out;
    fused_loss_kernel<<<GRID_A, THREADS_A>>>(x, out);
}

// round 8
// speedup vs baseline: 1.4525x; 1.4525x over previous
#include <cuda_runtime.h>
#include <math.h>

#define N_ROWS 8192
#define N_COLS 512
#define GRID_A 256
#define THREADS_A 256
#define WARPS_A 8              /* 256 blocks * 8 warps * 4 rows = 8192 rows */
#define NREP 8

#define SCALE_D   4294967296.0          /* 2^32 */
#define INV_SCALE (1.0 / 4294967296.0)

// Order-invariant integer accumulators (zero-init; last block resets).
__device__ unsigned long long g_col_ll[NREP][N_COLS];
__device__ unsigned long long g_S_ll;
__device__ int g_max_int;               // bit-cast float, values >= 0
__device__ unsigned int g_counter;

__global__ void __launch_bounds__(THREADS_A, 2)
fused_loss_kernel(const float* __restrict__ x, float* __restrict__ out) {
    __shared__ float s_colw[WARPS_A][N_COLS];   // 16 KB
    __shared__ float s_S[WARPS_A];
    __shared__ float s_M[WARPS_A];
    __shared__ double s_red[THREADS_A];
    __shared__ unsigned int s_last;

    const int tid = threadIdx.x;
    const int wid = tid >> 5;
    const int lid = tid & 31;

    // ---- streaming: warp owns 4 rows; 16 named float4 loads, ALL up front ----
    const int row0 = (blockIdx.x * WARPS_A + wid) * 4;
    const float4* p0 = reinterpret_cast<const float4*>(x + (size_t)row0 * N_COLS);
    const float4* p1 = p0 + 128;
    const float4* p2 = p0 + 256;
    const float4* p3 = p0 + 384;

    const float4 a0 = p0[lid];      const float4 a1 = p0[32 + lid];
    const float4 a2 = p0[64 + lid]; const float4 a3 = p0[96 + lid];
    const float4 b0 = p1[lid];      const float4 b1 = p1[32 + lid];
    const float4 b2 = p1[64 + lid]; const float4 b3 = p1[96 + lid];
    const float4 c0 = p2[lid];      const float4 c1 = p2[32 + lid];
    const float4 c2 = p2[64 + lid]; const float4 c3 = p2[96 + lid];
    const float4 d0 = p3[lid];      const float4 d1 = p3[32 + lid];
    const float4 d2 = p3[64 + lid]; const float4 d3 = p3[96 + lid];

    // column partials (4 rows summed), straight to smem
    float4 s0, s1, s2, s3;
    s0.x = a0.x + b0.x + c0.x + d0.x;  s0.y = a0.y + b0.y + c0.y + d0.y;
    s0.z = a0.z + b0.z + c0.z + d0.z;  s0.w = a0.w + b0.w + c0.w + d0.w;
    s1.x = a1.x + b1.x + c1.x + d1.x;  s1.y = a1.y + b1.y + c1.y + d1.y;
    s1.z = a1.z + b1.z + c1.z + d1.z;  s1.w = a1.w + b1.w + c1.w + d1.w;
    s2.x = a2.x + b2.x + c2.x + d2.x;  s2.y = a2.y + b2.y + c2.y + d2.y;
    s2.z = a2.z + b2.z + c2.z + d2.z;  s2.w = a2.w + b2.w + c2.w + d2.w;
    s3.x = a3.x + b3.x + c3.x + d3.x;  s3.y = a3.y + b3.y + c3.y + d3.y;
    s3.z = a3.z + b3.z + c3.z + d3.z;  s3.w = a3.w + b3.w + c3.w + d3.w;
    *reinterpret_cast<float4*>(&s_colw[wid][0   + lid * 4]) = s0;
    *reinterpret_cast<float4*>(&s_colw[wid][128 + lid * 4]) = s1;
    *reinterpret_cast<float4*>(&s_colw[wid][256 + lid * 4]) = s2;
    *reinterpret_cast<float4*>(&s_colw[wid][384 + lid * 4]) = s3;

    // per-row squared-norm lane partials
    float q0 = a0.x*a0.x + a0.y*a0.y + a0.z*a0.z + a0.w*a0.w
             + a1.x*a1.x + a1.y*a1.y + a1.z*a1.z + a1.w*a1.w
             + a2.x*a2.x + a2.y*a2.y + a2.z*a2.z + a2.w*a2.w
             + a3.x*a3.x + a3.y*a3.y + a3.z*a3.z + a3.w*a3.w;
    float q1 = b0.x*b0.x + b0.y*b0.y + b0.z*b0.z + b0.w*b0.w
             + b1.x*b1.x + b1.y*b1.y + b1.z*b1.z + b1.w*b1.w
             + b2.x*b2.x + b2.y*b2.y + b2.z*b2.z + b2.w*b2.w
             + b3.x*b3.x + b3.y*b3.y + b3.z*b3.z + b3.w*b3.w;
    float q2 = c0.x*c0.x + c0.y*c0.y + c0.z*c0.z + c0.w*c0.w
             + c1.x*c1.x + c1.y*c1.y + c1.z*c1.z + c1.w*c1.w
             + c2.x*c2.x + c2.y*c2.y + c2.z*c2.z + c2.w*c2.w
             + c3.x*c3.x + c3.y*c3.y + c3.z*c3.z + c3.w*c3.w;
    float q3 = d0.x*d0.x + d0.y*d0.y + d0.z*d0.z + d0.w*d0.w
             + d1.x*d1.x + d1.y*d1.y + d1.z*d1.z + d1.w*d1.w
             + d2.x*d2.x + d2.y*d2.y + d2.z*d2.z + d2.w*d2.w
             + d3.x*d3.x + d3.y*d3.y + d3.z*d3.z + d3.w*d3.w;

    #pragma unroll
    for (int off = 16; off > 0; off >>= 1) {
        q0 += __shfl_xor_sync(0xffffffffu, q0, off);
        q1 += __shfl_xor_sync(0xffffffffu, q1, off);
        q2 += __shfl_xor_sync(0xffffffffu, q2, off);
        q3 += __shfl_xor_sync(0xffffffffu, q3, off);
    }
    if (lid == 0) {
        s_S[wid] = (q0 + q1) + (q2 + q3);
        s_M[wid] = fmaxf(fmaxf(q0, q1), fmaxf(q2, q3));
    }
    __syncthreads();

    // ---- block epilogue: combine 8 warps, push int64 atomics (replicated) ----
    const int rep = blockIdx.x & (NREP - 1);
    #pragma unroll
    for (int k = 0; k < 2; ++k) {
        const int c = tid + k * THREADS_A;
        float v = 0.f;
        #pragma unroll
        for (int w = 0; w < WARPS_A; ++w) v += s_colw[w][c];
        atomicAdd(&g_col_ll[rep][c],
                  (unsigned long long)__double2ll_rn((double)v * SCALE_D));
    }
    if (tid == 0) {
        float Sp = 0.f, Mp = 0.f;
        #pragma unroll
        for (int w = 0; w < WARPS_A; ++w) {
            Sp += s_S[w];
            Mp = fmaxf(Mp, s_M[w]);
        }
        atomicAdd(&g_S_ll, (unsigned long long)__double2ll_rn((double)Sp * SCALE_D));
        atomicMax(&g_max_int, __float_as_int(Mp));
        __threadfence();
        const unsigned int prev = atomicAdd(&g_counter, 1u);
        s_last = (prev == (unsigned int)(GRID_A - 1)) ? 1u : 0u;
    }
    __syncthreads();
    if (s_last == 0u) return;

    // ---- finalize: last block; accumulators tiny and L2-hot ----
    __threadfence();

    long long t0 = 0ll, t1 = 0ll;
    #pragma unroll
    for (int r = 0; r < NREP; ++r) {
        t0 += (long long)g_col_ll[r][tid];
        t1 += (long long)g_col_ll[r][tid + THREADS_A];
    }
    const double e0 = (double)t0 * INV_SCALE;
    const double e1 = (double)t1 * INV_SCALE;

    s_red[tid] = e0 * e0 + e1 * e1;
    __syncthreads();
    #pragma unroll
    for (int s = THREADS_A / 2; s > 0; s >>= 1) {
        if (tid < s) s_red[tid] += s_red[tid + s];
        __syncthreads();
    }
    #pragma unroll
    for (int r = 0; r < NREP; ++r) {
        g_col_ll[r][tid] = 0ull;
        g_col_ll[r][tid + THREADS_A] = 0ull;
    }

    if (tid == 0) {
        const double ssq_total = s_red[0];
        const double S_total = (double)(long long)g_S_ll * INV_SCALE;
        const double maxsq = (double)__int_as_float(g_max_int);
        const double numer = (double)N_ROWS * S_total - ssq_total;
        const double norm = sqrt(maxsq);
        const double count = (double)N_ROWS * (double)(N_ROWS - 1) * 0.5;
        out[0] = (float)(numer / (norm * count));
        g_S_ll = 0ull;
        g_max_int = 0;
        g_counter = 0u;
    }
}

extern "C" void kernel_launch(void* const* d_in, const int* in_sizes, int n_in,
                              void* d_out, int out_size) {
    (void)in_sizes; (void)n_in; (void)out_size;
    const float* x = (const float*)d_in[0];
    float* out = (float*)d_out;
    fused_loss_kernel<<<GRID_A, THREADS_A>>>(x, out);
}